// round 14
// baseline (speedup 1.0000x reference)
#include <cuda_runtime.h>
#include <cstdint>

#define B_  2048
#define NI_ 15
#define MI_ 3

// ---------------------------------------------------------------------------
// Kernel A smem (floats): fsk[256][132]@0 (33792f); W bufs @33792f:
//   2 bufs x (2 hl x 16 k x 260) = 16640f; smalls from 50432f. 204800 B.
// ---------------------------------------------------------------------------
#define FS_STRIDE   132
#define WS_OFF_F    33792
#define WS_BUF_F    8320
#define WS_HL_F     4160
#define B1S_OFF_F   50432
#define B2S_OFF_F   50688
#define RSA_OFF_F   50944
#define RSB_OFF_F   51008
#define LMQ_OFF_F   51072
#define LMR_OFF_F   51136
#define SMEM_A_BYTES 204800

// Kernel B smem (floats): lKs[64][65]@0, Cs@4160, Ts@8320, smalls @12480.
#define BK_LKS_F    0
#define BK_CS_F     4160
#define BK_TS_F     8320
#define BK_LA_F     12480
#define BK_LB_F     12544
#define BK_RSA_F    12608
#define BK_RSB_F    12672
#define BK_RED_F    12736
#define SMEM_B_BYTES 51968

// W pre-split tf32 hi/lo, k-major: g_Ws[layer][hl][k][e], 1 MB (L2-resident).
__device__ float g_Ws[2 * 2 * 256 * 256];
// lK scratch: [B][64][64] f32, 33.5 MB.
__device__ float g_lK[(size_t)B_ * 64 * 64];

// ---------------------------------------------------------------------------
// helpers
// ---------------------------------------------------------------------------
__device__ __forceinline__ void tf32split(float x, uint32_t& hi, uint32_t& lo) {
    asm("cvt.rna.tf32.f32 %0, %1;" : "=r"(hi) : "f"(x));
    float d = x - __uint_as_float(hi);
    asm("cvt.rna.tf32.f32 %0, %1;" : "=r"(lo) : "f"(d));
}
__device__ __forceinline__ void mma8(float* d, const uint32_t* a, const uint32_t* b) {
    asm volatile(
        "mma.sync.aligned.m16n8k8.row.col.f32.tf32.tf32.f32 "
        "{%0,%1,%2,%3}, {%4,%5,%6,%7}, {%8,%9}, {%0,%1,%2,%3};"
        : "+f"(d[0]), "+f"(d[1]), "+f"(d[2]), "+f"(d[3])
        : "r"(a[0]), "r"(a[1]), "r"(a[2]), "r"(a[3]), "r"(b[0]), "r"(b[1]));
}
__device__ __forceinline__ unsigned long long pack2(float lo, float hi) {
    unsigned long long r;
    asm("mov.b64 %0, {%1,%2};" : "=l"(r) : "f"(lo), "f"(hi));
    return r;
}
__device__ __forceinline__ void unpack2(unsigned long long v, float& lo, float& hi) {
    asm("mov.b64 {%0,%1}, %2;" : "=f"(lo), "=f"(hi) : "l"(v));
}
__device__ __forceinline__ unsigned long long fma2(unsigned long long a,
                                                   unsigned long long b,
                                                   unsigned long long c) {
    unsigned long long d;
    asm("fma.rn.f32x2 %0, %1, %2, %3;" : "=l"(d) : "l"(a), "l"(b), "l"(c));
    return d;
}

// ---------------------------------------------------------------------------
// W prep: g_Ws[L][hl][k][e] = tf32 hi/lo of W_L[e][k]
// ---------------------------------------------------------------------------
__global__ void wprep_kernel(const float* __restrict__ W1, const float* __restrict__ W2) {
    for (int i = blockIdx.x * 256 + threadIdx.x; i < 262144; i += gridDim.x * 256) {
        int L  = i >> 17;
        int hl = (i >> 16) & 1;
        int k  = (i >> 8) & 255;
        int e  = i & 255;
        float w = (L ? W2 : W1)[(size_t)e * 256 + k];
        uint32_t hi, lo;
        tf32split(w, hi, lo);
        g_Ws[i] = __uint_as_float(hl ? lo : hi);
    }
}

// ---------------------------------------------------------------------------
// Kernel A: MLP (tf32 3-pass mma) + norms + Gram -> C (out) and lK (scratch).
// One block per batch, 256 threads. Structure = R10 (validated) + presplit W.
// ---------------------------------------------------------------------------
__global__ void __launch_bounds__(256, 1) mlp_gram_kernel(
    const float* __restrict__ sq, const float* __restrict__ sr,
    const float* __restrict__ mq, const float* __restrict__ mr,
    const float* __restrict__ b1, const float* __restrict__ b2,
    float* __restrict__ out)
{
    extern __shared__ float sm[];
    float* fsk = sm;
    float* b1s = sm + B1S_OFF_F;
    float* b2s = sm + B2S_OFF_F;
    float* rsA = sm + RSA_OFF_F;
    float* rsB = sm + RSB_OFF_F;
    float* lmq = sm + LMQ_OFF_F;
    float* lmr = sm + LMR_OFF_F;

    const int t   = threadIdx.x;
    const int l   = t & 31;
    const int w   = t >> 5;
    const int mg  = w & 1;               // rows 64*mg .. +63
    const int ng  = w >> 1;              // cols 64*ng .. +63
    const int lg  = l >> 2;              // 0..7
    const int tig = l & 3;               // 0..3
    const int b   = blockIdx.x;

    float* out_C = out + B_ + (size_t)B_ * 64 * 64;

    // ---- load x (coalesced) and transpose into fsk[k][row] ------------------
    {
        #pragma unroll
        for (int i = 0; i < 32; ++i) {
            int idx = t + i * 256;           // float4 index, 8192 total
            int row = idx >> 6;
            int d4  = (idx & 63) << 2;
            const float* src = (row < 64)
                ? sq + ((size_t)b * 64 + row) * 256
                : sr + ((size_t)b * 64 + (row - 64)) * 256;
            float4 v = *(const float4*)(src + d4);
            fsk[(d4 + 0) * FS_STRIDE + row] = v.x;
            fsk[(d4 + 1) * FS_STRIDE + row] = v.y;
            fsk[(d4 + 2) * FS_STRIDE + row] = v.z;
            fsk[(d4 + 3) * FS_STRIDE + row] = v.w;
        }
        b1s[t] = b1[t];
        b2s[t] = b2[t];
    }
    __syncthreads();

    // ---- 2-layer MLP via 3xTF32 mma.sync, W pre-split in global -------------
    float acc[4][8][4];

    for (int layer = 0; layer < 2; ++layer) {
        const float* Wsrc = g_Ws + (size_t)layer * 131072;  // [2 hl][256][256]

        #pragma unroll
        for (int m = 0; m < 4; ++m)
            #pragma unroll
            for (int n = 0; n < 8; ++n)
                #pragma unroll
                for (int j = 0; j < 4; ++j) acc[m][n][j] = 0.f;

        // stage chunk 0 (16 k, hi+lo) -> buf 0
        {
            float* wb = sm + WS_OFF_F;
            #pragma unroll
            for (int i = 0; i < 8; ++i) {
                int idx = t + i * 256;          // 2048 float4
                int hl = idx >> 10, rem = idx & 1023;
                int kk = rem >> 6, e4 = (rem & 63) << 2;
                *(float4*)&wb[hl * WS_HL_F + kk * 260 + e4] =
                    *(const float4*)&Wsrc[(size_t)hl * 65536 + kk * 256 + e4];
            }
        }
        __syncthreads();

        for (int c = 0; c < 16; ++c) {
            const int buf = c & 1, nb = buf ^ 1;
            if (c < 15) {
                float* wb = sm + WS_OFF_F + nb * WS_BUF_F;
                #pragma unroll
                for (int i = 0; i < 8; ++i) {
                    int idx = t + i * 256;
                    int hl = idx >> 10, rem = idx & 1023;
                    int kk = rem >> 6, e4 = (rem & 63) << 2;
                    *(float4*)&wb[hl * WS_HL_F + kk * 260 + e4] =
                        *(const float4*)&Wsrc[(size_t)hl * 65536 + ((c + 1) * 16 + kk) * 256 + e4];
                }
            }
            const float* wb = sm + WS_OFF_F + buf * WS_BUF_F;
            #pragma unroll
            for (int ksl = 0; ksl < 2; ++ksl) {
                // W fragments: straight LDS from pre-split hi/lo (no cvts)
                uint32_t whi[8][2], wlo[8][2];
                const int kr0 = (ksl * 8 + tig) * 260;
                #pragma unroll
                for (int n = 0; n < 8; ++n) {
                    int col = ng * 64 + n * 8 + lg;
                    whi[n][0] = __float_as_uint(wb[kr0 + col]);
                    whi[n][1] = __float_as_uint(wb[kr0 + 4 * 260 + col]);
                    wlo[n][0] = __float_as_uint(wb[WS_HL_F + kr0 + col]);
                    wlo[n][1] = __float_as_uint(wb[WS_HL_F + kr0 + 4 * 260 + col]);
                }
                const int kg = c * 16 + ksl * 8 + tig;
                #pragma unroll
                for (int m = 0; m < 4; ++m) {
                    const int r0 = mg * 64 + m * 16 + lg;
                    uint32_t ahi[4], alo[4];
                    tf32split(fsk[kg * FS_STRIDE + r0],           ahi[0], alo[0]);
                    tf32split(fsk[kg * FS_STRIDE + r0 + 8],       ahi[1], alo[1]);
                    tf32split(fsk[(kg + 4) * FS_STRIDE + r0],     ahi[2], alo[2]);
                    tf32split(fsk[(kg + 4) * FS_STRIDE + r0 + 8], ahi[3], alo[3]);
                    #pragma unroll
                    for (int n = 0; n < 8; ++n) {
                        mma8(acc[m][n], ahi, whi[n]);   // hi*hi
                        mma8(acc[m][n], alo, whi[n]);   // lo*hi
                        mma8(acc[m][n], ahi, wlo[n]);   // hi*lo
                    }
                }
            }
            __syncthreads();
        }

        // ---- epilogue: D-frags -> fsk k-major -------------------------------
        const float* bp = layer ? b2s : b1s;
        const bool relu = (layer == 0);
        #pragma unroll
        for (int m = 0; m < 4; ++m) {
            const int r0 = mg * 64 + m * 16 + lg;
            #pragma unroll
            for (int n = 0; n < 8; ++n) {
                const int cc = ng * 64 + n * 8 + 2 * tig;
                float bc0 = bp[cc], bc1 = bp[cc + 1];
                float v0 = acc[m][n][0] + bc0;
                float v1 = acc[m][n][1] + bc1;
                float v2 = acc[m][n][2] + bc0;
                float v3 = acc[m][n][3] + bc1;
                if (relu) {
                    v0 = fmaxf(v0, 0.f); v1 = fmaxf(v1, 0.f);
                    v2 = fmaxf(v2, 0.f); v3 = fmaxf(v3, 0.f);
                }
                fsk[cc * FS_STRIDE + r0]           = v0;
                fsk[(cc + 1) * FS_STRIDE + r0]     = v1;
                fsk[cc * FS_STRIDE + r0 + 8]       = v2;
                fsk[(cc + 1) * FS_STRIDE + r0 + 8] = v3;
            }
        }
        __syncthreads();
    }

    // ---- norms (2 threads per row over ALL 128 rows) + log marginals --------
    {
        int row = t >> 1, half = t & 1;
        float s = 0.f;
        #pragma unroll 8
        for (int i = 0; i < 128; ++i) {
            float v = fsk[(half * 128 + i) * FS_STRIDE + row];
            s += v * v;
        }
        s += __shfl_xor_sync(0xffffffffu, s, 1);
        if (half == 0) { if (row < 64) rsA[row] = s; else rsB[row - 64] = s; }
    }
    if (t < 64)       lmq[t] = __logf(fmaxf(mq[(size_t)b * 64 + t], 1e-8f));
    else if (t < 128) lmr[t - 64] = __logf(fmaxf(mr[(size_t)b * 64 + (t - 64)], 1e-8f));
    __syncthreads();

    // ---- Gram -> C (out), lK (scratch); 4k x 4m per thread ------------------
    {
        const int gx = t & 15, gy = t >> 4;
        unsigned long long g2[4][2];
        #pragma unroll
        for (int r = 0; r < 4; ++r) { g2[r][0] = 0ull; g2[r][1] = 0ull; }

        #pragma unroll 4
        for (int d = 0; d < 256; ++d) {
            const float4 xv = *(const float4*)&fsk[d * FS_STRIDE + 4 * gy];
            const ulonglong2 yv = *(const ulonglong2*)&fsk[d * FS_STRIDE + 64 + 4 * gx];
            float xr[4] = {xv.x, xv.y, xv.z, xv.w};
            #pragma unroll
            for (int r = 0; r < 4; ++r) {
                unsigned long long xp = pack2(xr[r], xr[r]);
                g2[r][0] = fma2(xp, yv.x, g2[r][0]);
                g2[r][1] = fma2(xp, yv.y, g2[r][1]);
            }
        }
        #pragma unroll
        for (int r = 0; r < 4; ++r) {
            int k = 4 * gy + r;
            float g[4];
            unpack2(g2[r][0], g[0], g[1]);
            unpack2(g2[r][1], g[2], g[3]);
            float nk = rsA[k];
            float lmqk = lmq[k];
            float4 c4, l4;
            c4.x = sqrtf(fmaxf(nk + rsB[4 * gx + 0] - 2.f * g[0], 0.f));
            c4.y = sqrtf(fmaxf(nk + rsB[4 * gx + 1] - 2.f * g[1], 0.f));
            c4.z = sqrtf(fmaxf(nk + rsB[4 * gx + 2] - 2.f * g[2], 0.f));
            c4.w = sqrtf(fmaxf(nk + rsB[4 * gx + 3] - 2.f * g[3], 0.f));
            l4.x = -c4.x * 20.0f + lmqk + lmr[4 * gx + 0];
            l4.y = -c4.y * 20.0f + lmqk + lmr[4 * gx + 1];
            l4.z = -c4.z * 20.0f + lmqk + lmr[4 * gx + 2];
            l4.w = -c4.w * 20.0f + lmqk + lmr[4 * gx + 3];
            *(float4*)&out_C[((size_t)b * 64 + k) * 64 + 4 * gx] = c4;
            *(float4*)&g_lK[((size_t)b * 64 + k) * 64 + 4 * gx] = l4;
        }
    }
}

// ---------------------------------------------------------------------------
// Kernel B: Sinkhorn + power iterations + outputs. 256 threads, 4 CTAs/SM.
// ---------------------------------------------------------------------------
__global__ void __launch_bounds__(256, 4) sink_kernel(float* __restrict__ out)
{
    extern __shared__ float sm[];
    float* lKs = sm + BK_LKS_F;
    float* Cs  = sm + BK_CS_F;
    float* Ts  = sm + BK_TS_F;
    float* la  = sm + BK_LA_F;
    float* lb  = sm + BK_LB_F;
    float* rsA = sm + BK_RSA_F;
    float* rsB = sm + BK_RSB_F;
    float* red = sm + BK_RED_F;

    const int t = threadIdx.x;
    const int b = blockIdx.x;

    float* out_sig = out;
    float* out_T   = out + B_;
    float* out_C   = out_T + (size_t)B_ * 64 * 64;
    float* out_c   = out_C + (size_t)B_ * 64 * 64;

    // ---- load lK and C into smem (stride 64 -> 65; SCALAR smem stores:
    //      row*65+c4 is odd-offset for odd rows, float4 STS would misalign) ---
    {
        #pragma unroll
        for (int i = 0; i < 4; ++i) {
            int idx = t + i * 256;            // 1024 float4
            int row = idx >> 4;
            int c4  = (idx & 15) << 2;
            float4 v = *(const float4*)&g_lK[(size_t)b * 4096 + row * 64 + c4];
            lKs[row * 65 + c4 + 0] = v.x;
            lKs[row * 65 + c4 + 1] = v.y;
            lKs[row * 65 + c4 + 2] = v.z;
            lKs[row * 65 + c4 + 3] = v.w;
            float4 u = *(const float4*)&out_C[(size_t)b * 4096 + row * 64 + c4];
            Cs[row * 65 + c4 + 0] = u.x;
            Cs[row * 65 + c4 + 1] = u.y;
            Cs[row * 65 + c4 + 2] = u.z;
            Cs[row * 65 + c4 + 3] = u.w;
        }
        if (t < 64) { la[t] = 0.f; lb[t] = 0.f; }
    }
    __syncthreads();

    // ---- Sinkhorn: 15 iterations, 4 threads per row/col ---------------------
    const int rk = t >> 2;
    const int q  = t & 3;
    for (int it = 0; it < NI_; ++it) {
        {   // la[k] = -lse_m(lK[k][m] + lb[m])
            float v[16], mx = -1e30f;
            #pragma unroll
            for (int j = 0; j < 16; ++j) {
                int m = q * 16 + j;
                v[j] = lKs[rk * 65 + m] + lb[m];
                mx = fmaxf(mx, v[j]);
            }
            mx = fmaxf(mx, __shfl_xor_sync(0xffffffffu, mx, 1));
            mx = fmaxf(mx, __shfl_xor_sync(0xffffffffu, mx, 2));
            float s = 0.f;
            #pragma unroll
            for (int j = 0; j < 16; ++j) s += __expf(v[j] - mx);
            s += __shfl_xor_sync(0xffffffffu, s, 1);
            s += __shfl_xor_sync(0xffffffffu, s, 2);
            if (q == 0) la[rk] = -(mx + __logf(s));
        }
        __syncthreads();
        {   // lb[m] = -lse_k(lK[k][m] + la[k])
            float v[16], mx = -1e30f;
            #pragma unroll
            for (int j = 0; j < 16; ++j) {
                int k = q * 16 + j;
                v[j] = lKs[k * 65 + rk] + la[k];
                mx = fmaxf(mx, v[j]);
            }
            mx = fmaxf(mx, __shfl_xor_sync(0xffffffffu, mx, 1));
            mx = fmaxf(mx, __shfl_xor_sync(0xffffffffu, mx, 2));
            float s = 0.f;
            #pragma unroll
            for (int j = 0; j < 16; ++j) s += __expf(v[j] - mx);
            s += __shfl_xor_sync(0xffffffffu, s, 1);
            s += __shfl_xor_sync(0xffffffffu, s, 2);
            if (q == 0) lb[rk] = -(mx + __logf(s));
        }
        __syncthreads();
    }

    // ---- T = exp(lK + la + lb) ---------------------------------------------
    {
        float lak = la[rk];
        #pragma unroll
        for (int j = 0; j < 16; ++j) {
            int m = q * 16 + j;
            Ts[rk * 65 + m] = __expf(lKs[rk * 65 + m] + lak + lb[m]);
        }
    }
    __syncthreads();

    // ---- power iterations ---------------------------------------------------
    for (int it = 0; it < MI_; ++it) {
        float s = 0.f;
        #pragma unroll
        for (int j = 0; j < 16; ++j) {
            int m = q * 16 + j;
            float v = Ts[rk * 65 + m];
            v *= v;
            Ts[rk * 65 + m] = v;
            s += v;
        }
        s += __shfl_xor_sync(0xffffffffu, s, 1);
        s += __shfl_xor_sync(0xffffffffu, s, 2);
        if (q == 0) rsA[rk] = s;
        __syncthreads();
        float dn = 1.f / (rsA[rk] + 1e-8f);
        #pragma unroll
        for (int j = 0; j < 16; ++j) Ts[rk * 65 + q * 16 + j] *= dn;
        __syncthreads();
        float cs = 0.f;
        #pragma unroll
        for (int j = 0; j < 16; ++j) cs += Ts[(q * 16 + j) * 65 + rk];
        cs += __shfl_xor_sync(0xffffffffu, cs, 1);
        cs += __shfl_xor_sync(0xffffffffu, cs, 2);
        if (q == 0) rsB[rk] = cs;
        __syncthreads();
        #pragma unroll
        for (int j = 0; j < 16; ++j) {
            int m = q * 16 + j;
            Ts[rk * 65 + m] /= (rsB[m] + 1e-8f);
        }
        __syncthreads();
    }

    // ---- c, sigmoid ---------------------------------------------------------
    {
        float s = 0.f;
        #pragma unroll
        for (int j = 0; j < 16; ++j) {
            int m = q * 16 + j;
            s += Ts[rk * 65 + m] * Cs[rk * 65 + m];
        }
        red[t] = s;
        __syncthreads();
        for (int off = 128; off > 0; off >>= 1) {
            if (t < off) red[t] += red[t + off];
            __syncthreads();
        }
        if (t == 0) {
            float c = red[0];
            out_c[b] = c;
            out_sig[b] = 1.f / (1.f + __expf(c));
        }
    }

    // ---- write T ------------------------------------------------------------
    {
        int row = t >> 2;
        int cb  = (t & 3) * 16;
        #pragma unroll
        for (int p = 0; p < 4; ++p) {
            float4 t4;
            t4.x = Ts[row * 65 + cb + 4 * p + 0];
            t4.y = Ts[row * 65 + cb + 4 * p + 1];
            t4.z = Ts[row * 65 + cb + 4 * p + 2];
            t4.w = Ts[row * 65 + cb + 4 * p + 3];
            *(float4*)&out_T[((size_t)b * 64 + row) * 64 + cb + 4 * p] = t4;
        }
    }
}

// ---------------------------------------------------------------------------
extern "C" void kernel_launch(void* const* d_in, const int* in_sizes, int n_in,
                              void* d_out, int out_size) {
    const float* sq = (const float*)d_in[0];
    const float* sr = (const float*)d_in[1];
    const float* mq = (const float*)d_in[2];
    const float* mr = (const float*)d_in[3];
    const float* W1 = (const float*)d_in[4];
    const float* b1 = (const float*)d_in[5];
    const float* W2 = (const float*)d_in[6];
    const float* b2 = (const float*)d_in[7];
    float* out = (float*)d_out;

    cudaFuncSetAttribute(mlp_gram_kernel, cudaFuncAttributeMaxDynamicSharedMemorySize, SMEM_A_BYTES);
    cudaFuncSetAttribute(sink_kernel,     cudaFuncAttributeMaxDynamicSharedMemorySize, SMEM_B_BYTES);

    wprep_kernel<<<128, 256>>>(W1, W2);
    mlp_gram_kernel<<<B_, 256, SMEM_A_BYTES>>>(sq, sr, mq, mr, b1, b2, out);
    sink_kernel<<<B_, 256, SMEM_B_BYTES>>>(out);
}

// round 15
// speedup vs baseline: 1.5322x; 1.5322x over previous
#include <cuda_runtime.h>
#include <cstdint>

#define B_  2048
#define NI_ 15
#define MI_ 3

// ---------------------------------------------------------------------------
// smem layout (bytes) — identical to R10:
//   [0, 135168): fsk = activation buffer, k-major [256 k][132 row] f32.
//   [135168, 201728): 2 x (32k x 260e) f32 W chunk buffers.
//     phase 2 aliases: Cs@135168, lKs@151808, Ts@168448 (each 64x65 f32)
//   [201728, 207360): biases + small arrays
// ---------------------------------------------------------------------------
#define FS_STRIDE   132
#define WS0_OFF_F   (135168 / 4)
#define WS1_OFF_F   (168448 / 4)
#define CS_OFF_F    (135168 / 4)
#define LKS_OFF_F   (151808 / 4)
#define TS_OFF_F    (168448 / 4)
#define B1S_OFF_F   (201728 / 4)
#define B2S_OFF_F   (202752 / 4)
#define LA_OFF_F    (203776 / 4)
#define LB_OFF_F    (204032 / 4)
#define RSA_OFF_F   (204288 / 4)
#define RSB_OFF_F   (204544 / 4)
#define LMQ_OFF_F   (204800 / 4)
#define LMR_OFF_F   (205056 / 4)
#define RED_OFF_F   (205312 / 4)
#define SMEM_BYTES  207360

// W pre-transposed k-major: g_Wt[layer][k][e], 512 KB (L2-resident).
__device__ float g_Wt[2 * 256 * 256];

// ---------------------------------------------------------------------------
// helpers
// ---------------------------------------------------------------------------
__device__ __forceinline__ uint32_t tf32of(float x) {
    uint32_t h;
    asm("cvt.rna.tf32.f32 %0, %1;" : "=r"(h) : "f"(x));
    return h;
}
__device__ __forceinline__ float tf32f(float x) {
    return __uint_as_float(tf32of(x));
}
__device__ __forceinline__ uint32_t packbf(float hi, float lo) {
    uint32_t r;
    asm("cvt.rn.bf16x2.f32 %0, %1, %2;" : "=r"(r) : "f"(hi), "f"(lo));
    return r;
}
// tf32 m16n8k8
__device__ __forceinline__ void mma8(float* d, const uint32_t* a, const uint32_t* b) {
    asm volatile(
        "mma.sync.aligned.m16n8k8.row.col.f32.tf32.tf32.f32 "
        "{%0,%1,%2,%3}, {%4,%5,%6,%7}, {%8,%9}, {%0,%1,%2,%3};"
        : "+f"(d[0]), "+f"(d[1]), "+f"(d[2]), "+f"(d[3])
        : "r"(a[0]), "r"(a[1]), "r"(a[2]), "r"(a[3]), "r"(b[0]), "r"(b[1]));
}
// bf16 m16n8k16
__device__ __forceinline__ void mma16(float* d, const uint32_t* a, const uint32_t* b) {
    asm volatile(
        "mma.sync.aligned.m16n8k16.row.col.f32.bf16.bf16.f32 "
        "{%0,%1,%2,%3}, {%4,%5,%6,%7}, {%8,%9}, {%0,%1,%2,%3};"
        : "+f"(d[0]), "+f"(d[1]), "+f"(d[2]), "+f"(d[3])
        : "r"(a[0]), "r"(a[1]), "r"(a[2]), "r"(a[3]), "r"(b[0]), "r"(b[1]));
}

// packed f32x2 helpers (Gram phase)
__device__ __forceinline__ unsigned long long pack2(float lo, float hi) {
    unsigned long long r;
    asm("mov.b64 %0, {%1,%2};" : "=l"(r) : "f"(lo), "f"(hi));
    return r;
}
__device__ __forceinline__ void unpack2(unsigned long long v, float& lo, float& hi) {
    asm("mov.b64 {%0,%1}, %2;" : "=f"(lo), "=f"(hi) : "l"(v));
}
__device__ __forceinline__ unsigned long long fma2(unsigned long long a,
                                                   unsigned long long b,
                                                   unsigned long long c) {
    unsigned long long d;
    asm("fma.rn.f32x2 %0, %1, %2, %3;" : "=l"(d) : "l"(a), "l"(b), "l"(c));
    return d;
}

// ---------------------------------------------------------------------------
// W transpose prep: g_Wt[L][k][e] = W_L[e][k]
// ---------------------------------------------------------------------------
__global__ void wprep_kernel(const float* __restrict__ W1, const float* __restrict__ W2) {
    for (int i = blockIdx.x * 256 + threadIdx.x; i < 131072; i += gridDim.x * 256) {
        int L = i >> 16;
        int r = i & 65535;
        int k = r >> 8;
        int e = r & 255;
        g_Wt[i] = (L ? W2 : W1)[(size_t)e * 256 + k];
    }
}

// ---------------------------------------------------------------------------
// Fused kernel: one block per batch, 256 threads.
// MLP: P1 tf32 k8 (xh*wh) + P2/P3 bf16 k16 (xl*w, x*wl).
// ---------------------------------------------------------------------------
__global__ void __launch_bounds__(256, 1) fused_kernel(
    const float* __restrict__ sq, const float* __restrict__ sr,
    const float* __restrict__ mq, const float* __restrict__ mr,
    const float* __restrict__ b1, const float* __restrict__ b2,
    float* __restrict__ out)
{
    extern __shared__ float sm[];
    float* fsk = sm;                     // k-major activations [256][132]
    float* ws0 = sm + WS0_OFF_F;
    float* ws1 = sm + WS1_OFF_F;
    float* b1s = sm + B1S_OFF_F;
    float* b2s = sm + B2S_OFF_F;
    float* la  = sm + LA_OFF_F;
    float* lb  = sm + LB_OFF_F;
    float* rsA = sm + RSA_OFF_F;
    float* rsB = sm + RSB_OFF_F;
    float* lmq = sm + LMQ_OFF_F;
    float* lmr = sm + LMR_OFF_F;
    float* red = sm + RED_OFF_F;
    float* Cs  = sm + CS_OFF_F;
    float* lKs = sm + LKS_OFF_F;
    float* Ts  = sm + TS_OFF_F;

    const int t   = threadIdx.x;
    const int l   = t & 31;
    const int w   = t >> 5;
    const int mg  = w & 1;               // M group: rows 64*mg .. +63
    const int ng  = w >> 1;              // N group: cols 64*ng .. +63
    const int lg  = l >> 2;              // 0..7
    const int tig = l & 3;               // 0..3
    const int b   = blockIdx.x;

    float* out_sig = out;
    float* out_T   = out + B_;
    float* out_C   = out_T + (size_t)B_ * 64 * 64;
    float* out_c   = out_C + (size_t)B_ * 64 * 64;

    // ---- load x (coalesced) and transpose into fsk[k][row] ------------------
    {
        #pragma unroll
        for (int i = 0; i < 32; ++i) {
            int idx = t + i * 256;           // float4 index, 8192 total
            int row = idx >> 6;
            int d4  = (idx & 63) << 2;
            const float* src = (row < 64)
                ? sq + ((size_t)b * 64 + row) * 256
                : sr + ((size_t)b * 64 + (row - 64)) * 256;
            float4 v = *(const float4*)(src + d4);
            fsk[(d4 + 0) * FS_STRIDE + row] = v.x;
            fsk[(d4 + 1) * FS_STRIDE + row] = v.y;
            fsk[(d4 + 2) * FS_STRIDE + row] = v.z;
            fsk[(d4 + 3) * FS_STRIDE + row] = v.w;
        }
        b1s[t] = b1[t];
        b2s[t] = b2[t];
    }
    __syncthreads();

    // ---- 2-layer MLP --------------------------------------------------------
    float acc[4][8][4];

    for (int layer = 0; layer < 2; ++layer) {
        const float* Wt = g_Wt + layer * 65536;

        #pragma unroll
        for (int m = 0; m < 4; ++m)
            #pragma unroll
            for (int n = 0; n < 8; ++n)
                #pragma unroll
                for (int j = 0; j < 4; ++j) acc[m][n][j] = 0.f;

        // stage chunk 0 -> ws0
        #pragma unroll
        for (int i = 0; i < 8; ++i) {
            int idx = t + i * 256;
            int kk = idx >> 6, e4 = (idx & 63) << 2;
            *(float4*)&ws0[kk * 260 + e4] = *(const float4*)&Wt[kk * 256 + e4];
        }
        __syncthreads();

        for (int c = 0; c < 8; ++c) {
            float* wcur = (c & 1) ? ws1 : ws0;
            float* wnxt = (c & 1) ? ws0 : ws1;
            if (c < 7) {
                #pragma unroll
                for (int i = 0; i < 8; ++i) {
                    int idx = t + i * 256;
                    int kk = idx >> 6, e4 = (idx & 63) << 2;
                    *(float4*)&wnxt[kk * 260 + e4] =
                        *(const float4*)&Wt[(c + 1) * 8192 + kk * 256 + e4];
                }
            }
            #pragma unroll
            for (int kw = 0; kw < 2; ++kw) {
                const int kb = kw * 16;          // k16 window base within chunk
                const int kg = c * 32 + kb;      // global k base

                // ======== pass 1: tf32 xh*wh (2 x k8 steps) ==================
                {
                    uint32_t wt[8][2][2];
                    #pragma unroll
                    for (int n = 0; n < 8; ++n) {
                        int col = ng * 64 + n * 8 + lg;
                        wt[n][0][0] = tf32of(wcur[(kb + tig)      * 260 + col]);
                        wt[n][0][1] = tf32of(wcur[(kb + tig + 4)  * 260 + col]);
                        wt[n][1][0] = tf32of(wcur[(kb + tig + 8)  * 260 + col]);
                        wt[n][1][1] = tf32of(wcur[(kb + tig + 12) * 260 + col]);
                    }
                    #pragma unroll
                    for (int m = 0; m < 4; ++m) {
                        const int r0 = mg * 64 + m * 16 + lg;
                        uint32_t a0[4], a1[4];
                        a0[0] = tf32of(fsk[(kg + tig)      * FS_STRIDE + r0]);
                        a0[1] = tf32of(fsk[(kg + tig)      * FS_STRIDE + r0 + 8]);
                        a0[2] = tf32of(fsk[(kg + tig + 4)  * FS_STRIDE + r0]);
                        a0[3] = tf32of(fsk[(kg + tig + 4)  * FS_STRIDE + r0 + 8]);
                        a1[0] = tf32of(fsk[(kg + tig + 8)  * FS_STRIDE + r0]);
                        a1[1] = tf32of(fsk[(kg + tig + 8)  * FS_STRIDE + r0 + 8]);
                        a1[2] = tf32of(fsk[(kg + tig + 12) * FS_STRIDE + r0]);
                        a1[3] = tf32of(fsk[(kg + tig + 12) * FS_STRIDE + r0 + 8]);
                        #pragma unroll
                        for (int n = 0; n < 8; ++n) mma8(acc[m][n], a0, wt[n][0]);
                        #pragma unroll
                        for (int n = 0; n < 8; ++n) mma8(acc[m][n], a1, wt[n][1]);
                    }
                }
                // ======== passes 2&3: bf16 k16 (xl*w  and  x*wl) =============
                {
                    uint32_t wb[8][2], wl[8][2];
                    #pragma unroll
                    for (int n = 0; n < 8; ++n) {
                        int col = ng * 64 + n * 8 + lg;
                        float w0 = wcur[(kb + 2 * tig)     * 260 + col];
                        float w1 = wcur[(kb + 2 * tig + 1) * 260 + col];
                        float w2 = wcur[(kb + 2 * tig + 8) * 260 + col];
                        float w3 = wcur[(kb + 2 * tig + 9) * 260 + col];
                        wb[n][0] = packbf(w1, w0);
                        wb[n][1] = packbf(w3, w2);
                        wl[n][0] = packbf(w1 - tf32f(w1), w0 - tf32f(w0));
                        wl[n][1] = packbf(w3 - tf32f(w3), w2 - tf32f(w2));
                    }
                    #pragma unroll
                    for (int m = 0; m < 4; ++m) {
                        const int r0 = mg * 64 + m * 16 + lg;
                        float x0 = fsk[(kg + 2 * tig)     * FS_STRIDE + r0];
                        float x1 = fsk[(kg + 2 * tig + 1) * FS_STRIDE + r0];
                        float x2 = fsk[(kg + 2 * tig + 8) * FS_STRIDE + r0];
                        float x3 = fsk[(kg + 2 * tig + 9) * FS_STRIDE + r0];
                        float y0 = fsk[(kg + 2 * tig)     * FS_STRIDE + r0 + 8];
                        float y1 = fsk[(kg + 2 * tig + 1) * FS_STRIDE + r0 + 8];
                        float y2 = fsk[(kg + 2 * tig + 8) * FS_STRIDE + r0 + 8];
                        float y3 = fsk[(kg + 2 * tig + 9) * FS_STRIDE + r0 + 8];
                        uint32_t ax[4], al[4];
                        ax[0] = packbf(x1, x0);
                        ax[1] = packbf(y1, y0);
                        ax[2] = packbf(x3, x2);
                        ax[3] = packbf(y3, y2);
                        al[0] = packbf(x1 - tf32f(x1), x0 - tf32f(x0));
                        al[1] = packbf(y1 - tf32f(y1), y0 - tf32f(y0));
                        al[2] = packbf(x3 - tf32f(x3), x2 - tf32f(x2));
                        al[3] = packbf(y3 - tf32f(y3), y2 - tf32f(y2));
                        #pragma unroll
                        for (int n = 0; n < 8; ++n) mma16(acc[m][n], al, wb[n]);
                        #pragma unroll
                        for (int n = 0; n < 8; ++n) mma16(acc[m][n], ax, wl[n]);
                    }
                }
            }
            __syncthreads();
        }

        // ---- epilogue: D-frags -> fsk k-major (identical to R10) ------------
        const float* bp = layer ? b2s : b1s;
        const bool relu = (layer == 0);
        #pragma unroll
        for (int m = 0; m < 4; ++m) {
            const int r0 = mg * 64 + m * 16 + lg;
            #pragma unroll
            for (int n = 0; n < 8; ++n) {
                const int cc = ng * 64 + n * 8 + 2 * tig;
                float bc0 = bp[cc], bc1 = bp[cc + 1];
                float v0 = acc[m][n][0] + bc0;
                float v1 = acc[m][n][1] + bc1;
                float v2 = acc[m][n][2] + bc0;
                float v3 = acc[m][n][3] + bc1;
                if (relu) {
                    v0 = fmaxf(v0, 0.f); v1 = fmaxf(v1, 0.f);
                    v2 = fmaxf(v2, 0.f); v3 = fmaxf(v3, 0.f);
                }
                fsk[cc * FS_STRIDE + r0]           = v0;
                fsk[(cc + 1) * FS_STRIDE + r0]     = v1;
                fsk[cc * FS_STRIDE + r0 + 8]       = v2;
                fsk[(cc + 1) * FS_STRIDE + r0 + 8] = v3;
            }
        }
        __syncthreads();
    }

    // ---- norms (2 threads per row over ALL 128 rows) + log marginals --------
    {
        int row = t >> 1, half = t & 1;      // row 0..127 at 256 threads
        float s = 0.f;
        #pragma unroll 8
        for (int i = 0; i < 128; ++i) {
            float v = fsk[(half * 128 + i) * FS_STRIDE + row];
            s += v * v;
        }
        s += __shfl_xor_sync(0xffffffffu, s, 1);
        if (half == 0) { if (row < 64) rsA[row] = s; else rsB[row - 64] = s; }
    }
    if (t < 64)       { lmq[t] = __logf(fmaxf(mq[(size_t)b * 64 + t], 1e-8f)); la[t] = 0.f; }
    else if (t < 128) { lmr[t - 64] = __logf(fmaxf(mr[(size_t)b * 64 + (t - 64)], 1e-8f)); lb[t - 64] = 0.f; }
    __syncthreads();

    // ---- Gram -> C, lK (reads fsk k-major); 4k x 4m per thread --------------
    {
        const int gx = t & 15, gy = t >> 4;
        unsigned long long g2[4][2];
        #pragma unroll
        for (int r = 0; r < 4; ++r) { g2[r][0] = 0ull; g2[r][1] = 0ull; }

        #pragma unroll 4
        for (int d = 0; d < 256; ++d) {
            const float4 xv = *(const float4*)&fsk[d * FS_STRIDE + 4 * gy];
            const ulonglong2 yv = *(const ulonglong2*)&fsk[d * FS_STRIDE + 64 + 4 * gx];
            float xr[4] = {xv.x, xv.y, xv.z, xv.w};
            #pragma unroll
            for (int r = 0; r < 4; ++r) {
                unsigned long long xp = pack2(xr[r], xr[r]);
                g2[r][0] = fma2(xp, yv.x, g2[r][0]);
                g2[r][1] = fma2(xp, yv.y, g2[r][1]);
            }
        }
        #pragma unroll
        for (int r = 0; r < 4; ++r) {
            int k = 4 * gy + r;
            float g[4];
            unpack2(g2[r][0], g[0], g[1]);
            unpack2(g2[r][1], g[2], g[3]);
            float nk = rsA[k];
            float lmqk = lmq[k];
            float4 c4;
            c4.x = sqrtf(fmaxf(nk + rsB[4 * gx + 0] - 2.f * g[0], 0.f));
            c4.y = sqrtf(fmaxf(nk + rsB[4 * gx + 1] - 2.f * g[1], 0.f));
            c4.z = sqrtf(fmaxf(nk + rsB[4 * gx + 2] - 2.f * g[2], 0.f));
            c4.w = sqrtf(fmaxf(nk + rsB[4 * gx + 3] - 2.f * g[3], 0.f));
            Cs[k * 65 + 4 * gx + 0] = c4.x;
            Cs[k * 65 + 4 * gx + 1] = c4.y;
            Cs[k * 65 + 4 * gx + 2] = c4.z;
            Cs[k * 65 + 4 * gx + 3] = c4.w;
            lKs[k * 65 + 4 * gx + 0] = -c4.x * 20.0f + lmqk + lmr[4 * gx + 0];
            lKs[k * 65 + 4 * gx + 1] = -c4.y * 20.0f + lmqk + lmr[4 * gx + 1];
            lKs[k * 65 + 4 * gx + 2] = -c4.z * 20.0f + lmqk + lmr[4 * gx + 2];
            lKs[k * 65 + 4 * gx + 3] = -c4.w * 20.0f + lmqk + lmr[4 * gx + 3];
            *(float4*)&out_C[((size_t)b * 64 + k) * 64 + 4 * gx] = c4;
        }
    }
    __syncthreads();

    // ---- Sinkhorn: 15 iterations, 4 threads per row/col ---------------------
    const int rk = t >> 2;
    const int q  = t & 3;
    for (int it = 0; it < NI_; ++it) {
        {   // la[k] = -lse_m(lK[k][m] + lb[m])
            float v[16], mx = -1e30f;
            #pragma unroll
            for (int j = 0; j < 16; ++j) {
                int m = q * 16 + j;
                v[j] = lKs[rk * 65 + m] + lb[m];
                mx = fmaxf(mx, v[j]);
            }
            mx = fmaxf(mx, __shfl_xor_sync(0xffffffffu, mx, 1));
            mx = fmaxf(mx, __shfl_xor_sync(0xffffffffu, mx, 2));
            float s = 0.f;
            #pragma unroll
            for (int j = 0; j < 16; ++j) s += __expf(v[j] - mx);
            s += __shfl_xor_sync(0xffffffffu, s, 1);
            s += __shfl_xor_sync(0xffffffffu, s, 2);
            if (q == 0) la[rk] = -(mx + __logf(s));
        }
        __syncthreads();
        {   // lb[m] = -lse_k(lK[k][m] + la[k])
            float v[16], mx = -1e30f;
            #pragma unroll
            for (int j = 0; j < 16; ++j) {
                int k = q * 16 + j;
                v[j] = lKs[k * 65 + rk] + la[k];
                mx = fmaxf(mx, v[j]);
            }
            mx = fmaxf(mx, __shfl_xor_sync(0xffffffffu, mx, 1));
            mx = fmaxf(mx, __shfl_xor_sync(0xffffffffu, mx, 2));
            float s = 0.f;
            #pragma unroll
            for (int j = 0; j < 16; ++j) s += __expf(v[j] - mx);
            s += __shfl_xor_sync(0xffffffffu, s, 1);
            s += __shfl_xor_sync(0xffffffffu, s, 2);
            if (q == 0) lb[rk] = -(mx + __logf(s));
        }
        __syncthreads();
    }

    // ---- T = exp(lK + la + lb) ---------------------------------------------
    {
        float lak = la[rk];
        #pragma unroll
        for (int j = 0; j < 16; ++j) {
            int m = q * 16 + j;
            Ts[rk * 65 + m] = __expf(lKs[rk * 65 + m] + lak + lb[m]);
        }
    }
    __syncthreads();

    // ---- power iterations ---------------------------------------------------
    for (int it = 0; it < MI_; ++it) {
        float s = 0.f;
        #pragma unroll
        for (int j = 0; j < 16; ++j) {
            int m = q * 16 + j;
            float v = Ts[rk * 65 + m];
            v *= v;
            Ts[rk * 65 + m] = v;
            s += v;
        }
        s += __shfl_xor_sync(0xffffffffu, s, 1);
        s += __shfl_xor_sync(0xffffffffu, s, 2);
        if (q == 0) rsA[rk] = s;
        __syncthreads();
        float dn = 1.f / (rsA[rk] + 1e-8f);
        #pragma unroll
        for (int j = 0; j < 16; ++j) Ts[rk * 65 + q * 16 + j] *= dn;
        __syncthreads();
        float cs = 0.f;
        #pragma unroll
        for (int j = 0; j < 16; ++j) cs += Ts[(q * 16 + j) * 65 + rk];
        cs += __shfl_xor_sync(0xffffffffu, cs, 1);
        cs += __shfl_xor_sync(0xffffffffu, cs, 2);
        if (q == 0) rsB[rk] = cs;
        __syncthreads();
        #pragma unroll
        for (int j = 0; j < 16; ++j) {
            int m = q * 16 + j;
            Ts[rk * 65 + m] /= (rsB[m] + 1e-8f);
        }
        __syncthreads();
    }

    // ---- c, sigmoid ---------------------------------------------------------
    {
        float s = 0.f;
        #pragma unroll
        for (int j = 0; j < 16; ++j) {
            int m = q * 16 + j;
            s += Ts[rk * 65 + m] * Cs[rk * 65 + m];
        }
        red[t] = s;
        __syncthreads();
        for (int off = 128; off > 0; off >>= 1) {
            if (t < off) red[t] += red[t + off];
            __syncthreads();
        }
        if (t == 0) {
            float c = red[0];
            out_c[b] = c;
            out_sig[b] = 1.f / (1.f + __expf(c));
        }
    }

    // ---- write T ------------------------------------------------------------
    {
        int row = t >> 2;
        int cb  = (t & 3) * 16;
        #pragma unroll
        for (int p = 0; p < 4; ++p) {
            float4 t4;
            t4.x = Ts[row * 65 + cb + 4 * p + 0];
            t4.y = Ts[row * 65 + cb + 4 * p + 1];
            t4.z = Ts[row * 65 + cb + 4 * p + 2];
            t4.w = Ts[row * 65 + cb + 4 * p + 3];
            *(float4*)&out_T[((size_t)b * 64 + row) * 64 + cb + 4 * p] = t4;
        }
    }
}

// ---------------------------------------------------------------------------
extern "C" void kernel_launch(void* const* d_in, const int* in_sizes, int n_in,
                              void* d_out, int out_size) {
    const float* sq = (const float*)d_in[0];
    const float* sr = (const float*)d_in[1];
    const float* mq = (const float*)d_in[2];
    const float* mr = (const float*)d_in[3];
    const float* W1 = (const float*)d_in[4];
    const float* b1 = (const float*)d_in[5];
    const float* W2 = (const float*)d_in[6];
    const float* b2 = (const float*)d_in[7];
    float* out = (float*)d_out;

    cudaFuncSetAttribute(fused_kernel, cudaFuncAttributeMaxDynamicSharedMemorySize, SMEM_BYTES);

    wprep_kernel<<<64, 256>>>(W1, W2);
    fused_kernel<<<B_, 256, SMEM_BYTES>>>(sq, sr, mq, mr, b1, b2, out);
}